// round 7
// baseline (speedup 1.0000x reference)
#include <cuda_runtime.h>
#include <cuda_bf16.h>

// out = -0.1f * x over 67,108,864 fp32 elements (256 MiB in + 256 MiB out).
// Pure HBM stream at ~82% of spec. This round: 256-bit global accesses
// (PTX v8.f32 -> LDG.E.256 / STG.E.256 on sm_103a) — longest possible
// per-instruction bursts; 2 front-batched 256b loads per thread.

#define ITEMS 2       // 256-bit chunks per thread
#define THREADS 512
#define FLOATS_PER_CHUNK 8
#define TILE_FLOATS (THREADS * ITEMS * FLOATS_PER_CHUNK)  // 8192 floats / block

__device__ __forceinline__ void ldg256_cs(const float* __restrict__ p, float* v) {
    asm volatile(
        "ld.global.cs.v8.f32 {%0, %1, %2, %3, %4, %5, %6, %7}, [%8];"
        : "=f"(v[0]), "=f"(v[1]), "=f"(v[2]), "=f"(v[3]),
          "=f"(v[4]), "=f"(v[5]), "=f"(v[6]), "=f"(v[7])
        : "l"(p));
}

__device__ __forceinline__ void stg256_cs(float* __restrict__ p, const float* v) {
    asm volatile(
        "st.global.cs.v8.f32 [%0], {%1, %2, %3, %4, %5, %6, %7, %8};"
        :: "l"(p),
           "f"(v[0]), "f"(v[1]), "f"(v[2]), "f"(v[3]),
           "f"(v[4]), "f"(v[5]), "f"(v[6]), "f"(v[7])
        : "memory");
}

// Exact-fit: n is a multiple of TILE_FLOATS; no bounds checks.
__global__ void __launch_bounds__(THREADS)
scale_kernel_v8(const float* __restrict__ x,
                float* __restrict__ out) {
    long long base = (long long)blockIdx.x * TILE_FLOATS
                   + (long long)threadIdx.x * FLOATS_PER_CHUNK;

    float v[ITEMS][FLOATS_PER_CHUNK];
    #pragma unroll
    for (int k = 0; k < ITEMS; k++) {
        ldg256_cs(x + base + (long long)k * (THREADS * FLOATS_PER_CHUNK), v[k]);
    }

    #pragma unroll
    for (int k = 0; k < ITEMS; k++) {
        float r[FLOATS_PER_CHUNK];
        #pragma unroll
        for (int j = 0; j < FLOATS_PER_CHUNK; j++) {
            r[j] = -0.1f * v[k][j];
        }
        stg256_cs(out + base + (long long)k * (THREADS * FLOATS_PER_CHUNK), r);
    }
}

// Guarded float4 kernel for sizes that don't divide into whole tiles.
#define G_ITEMS 2
#define G_TILE (THREADS * G_ITEMS)
__global__ void __launch_bounds__(THREADS)
scale_kernel_guarded(const float4* __restrict__ x,
                     float4* __restrict__ out,
                     int n4) {
    int base = blockIdx.x * G_TILE + threadIdx.x;
    #pragma unroll
    for (int k = 0; k < G_ITEMS; k++) {
        int i = base + k * THREADS;
        if (i < n4) {
            float4 v = __ldcs(&x[i]);
            float4 r;
            r.x = -0.1f * v.x;
            r.y = -0.1f * v.y;
            r.z = -0.1f * v.z;
            r.w = -0.1f * v.w;
            __stcs(&out[i], r);
        }
    }
}

// Scalar tail for element counts not divisible by 4.
__global__ void scale_kernel_tail(const float* __restrict__ x,
                                  float* __restrict__ out,
                                  int start, int n) {
    int i = start + blockIdx.x * blockDim.x + threadIdx.x;
    if (i < n) {
        out[i] = -0.1f * x[i];
    }
}

extern "C" void kernel_launch(void* const* d_in, const int* in_sizes, int n_in,
                              void* d_out, int out_size) {
    const float* x = (const float*)d_in[0];
    float* out = (float*)d_out;
    int n = in_sizes[0];

    if (n > 0 && n % TILE_FLOATS == 0) {
        scale_kernel_v8<<<n / TILE_FLOATS, THREADS>>>(x, out);
        return;
    }

    int n4 = n / 4;
    if (n4 > 0) {
        int blocks = (n4 + G_TILE - 1) / G_TILE;
        scale_kernel_guarded<<<blocks, THREADS>>>(
            (const float4*)x, (float4*)out, n4);
    }
    int tail_start = n4 * 4;
    int tail = n - tail_start;
    if (tail > 0) {
        scale_kernel_tail<<<1, 256>>>(x, out, tail_start, n);
    }
}

// round 8
// speedup vs baseline: 1.0047x; 1.0047x over previous
#include <cuda_runtime.h>
#include <cuda_bf16.h>

// out = -0.1f * x over 67,108,864 fp32 elements (256 MiB in + 256 MiB out).
// Pure HBM stream at the r+w turnaround ceiling (~82% of 8TB/s spec).
// Sweep results (kernel us): 4x256=74.7, 4x512=74.0, 2x512=73.8, 8x256=75.2,
// v8 2x512=74.6, persistent=80.1. This round: ITEMS=2 x THREADS=256 —
// finest CTA granularity (8 warps) at the measured-best per-thread load depth.

#define ITEMS 2
#define THREADS 256
#define TILE (THREADS * ITEMS)

// Exact-fit: grid covers n4 exactly, no bounds checks.
__global__ void __launch_bounds__(THREADS)
scale_kernel_exact(const float4* __restrict__ x,
                   float4* __restrict__ out) {
    int base = blockIdx.x * TILE + threadIdx.x;

    float4 v[ITEMS];
    #pragma unroll
    for (int k = 0; k < ITEMS; k++) {
        v[k] = __ldcs(&x[base + k * THREADS]);
    }

    #pragma unroll
    for (int k = 0; k < ITEMS; k++) {
        float4 r;
        r.x = -0.1f * v[k].x;
        r.y = -0.1f * v[k].y;
        r.z = -0.1f * v[k].z;
        r.w = -0.1f * v[k].w;
        __stcs(&out[base + k * THREADS], r);
    }
}

// Guarded generic kernel for sizes that don't divide into whole tiles.
__global__ void __launch_bounds__(THREADS)
scale_kernel_guarded(const float4* __restrict__ x,
                     float4* __restrict__ out,
                     int n4) {
    int base = blockIdx.x * TILE + threadIdx.x;
    #pragma unroll
    for (int k = 0; k < ITEMS; k++) {
        int i = base + k * THREADS;
        if (i < n4) {
            float4 v = __ldcs(&x[i]);
            float4 r;
            r.x = -0.1f * v.x;
            r.y = -0.1f * v.y;
            r.z = -0.1f * v.z;
            r.w = -0.1f * v.w;
            __stcs(&out[i], r);
        }
    }
}

// Scalar tail for element counts not divisible by 4.
__global__ void scale_kernel_tail(const float* __restrict__ x,
                                  float* __restrict__ out,
                                  int start, int n) {
    int i = start + blockIdx.x * blockDim.x + threadIdx.x;
    if (i < n) {
        out[i] = -0.1f * x[i];
    }
}

extern "C" void kernel_launch(void* const* d_in, const int* in_sizes, int n_in,
                              void* d_out, int out_size) {
    const float* x = (const float*)d_in[0];
    float* out = (float*)d_out;
    int n = in_sizes[0];

    int n4 = n / 4;
    if (n4 > 0) {
        if (n4 % TILE == 0) {
            scale_kernel_exact<<<n4 / TILE, THREADS>>>(
                (const float4*)x, (float4*)out);
        } else {
            int blocks = (n4 + TILE - 1) / TILE;
            scale_kernel_guarded<<<blocks, THREADS>>>(
                (const float4*)x, (float4*)out, n4);
        }
    }
    int tail_start = n4 * 4;
    int tail = n - tail_start;
    if (tail > 0) {
        scale_kernel_tail<<<1, 256>>>(x, out, tail_start, n);
    }
}